// round 6
// baseline (speedup 1.0000x reference)
#include <cuda_runtime.h>
#include <mma.h>
#include <math.h>
#include <cstdint>

using namespace nvcuda;

// ---------------------------------------------------------------------------
// GaborAutoencoder: encoder via EXACT int8 IMMA (4-limb base-128, 10 passes,
// 4 weight-grouped int32 accumulators) -> wavelet synthesis.
// Rationale: sm_103 legacy-path FP-MMA accumulator rounds (~2^-14/op, R3-R5
// evidence); integer accumulation is bit-exact by construction.
// ---------------------------------------------------------------------------

__device__ float g_h1[4096 * 1024];
__device__ float g_h2[4096 * 512];
__device__ float g_h3[4096 * 256];
__device__ float g_p [4096 * 160];

// int8 limb planes (4 planes per tensor, plane = full tensor)
__device__ int8_t g_xq [4ull * 4096 * 4096];
__device__ int8_t g_h1q[4ull * 4096 * 1024];
__device__ int8_t g_h2q[4ull * 4096 * 512];
__device__ int8_t g_h3q[4ull * 4096 * 256];
__device__ int8_t g_w1q[4ull * 1024 * 4096];
__device__ int8_t g_w2q[4ull * 512 * 1024];
__device__ int8_t g_w3q[4ull * 256 * 512];
__device__ int8_t g_w4q[4ull * 160 * 256];

// ---------------------------------------------------------------------------
// Quantize float -> 4 int8 limbs, base 128. invS is a power of two.
// a/sA = q; u0 = 128q; v_t = rint(u_t); u_{t+1} = (u_t - v_t)*128. All exact.
// ---------------------------------------------------------------------------
__global__ __launch_bounds__(256)
void quant_kernel(const float* __restrict__ src, int8_t* __restrict__ dst,
                  float invS, int n4, size_t plane)
{
    int i = blockIdx.x * 256 + threadIdx.x;
    if (i >= n4) return;
    float4 v = ((const float4*)src)[i];
    float c[4] = {v.x, v.y, v.z, v.w};
    uint32_t lim[4] = {0u, 0u, 0u, 0u};
#pragma unroll
    for (int e = 0; e < 4; e++) {
        float u = c[e] * invS * 128.f;
#pragma unroll
        for (int t = 0; t < 4; t++) {
            float vv = rintf(u);
            int iv = (int)vv;
            lim[t] |= (uint32_t)(iv & 0xFF) << (e * 8);
            u = (u - vv) * 128.f;
        }
    }
#pragma unroll
    for (int t = 0; t < 4; t++)
        *(uint32_t*)(dst + t * plane + (size_t)i * 4) = lim[t];
}

// ---------------------------------------------------------------------------
// Exact-int8 GEMM: C[m,n] = act( S * sum_groups(...) + bias[n] )
// A limbs: M x K planes; B limbs: N x K planes (both K contiguous).
// Block tile 128(M) x 64(N), BK=32, 256 threads, 8 warps (2M x 4N),
// warp tile 64 x 16. Int accumulators g[group][mi], group = a_limb + b_limb.
// ---------------------------------------------------------------------------
#define LDQ 48
#define ATILE (128 * LDQ)                 // 6144 B
#define BTILE (64 * LDQ)                  // 3072 B
#define STAGE (4 * ATILE + 4 * BTILE)     // 36864 B
#define GEMM_SMEM (2 * STAGE)             // 73728 B

template<bool RELU, bool GUARD>
__global__ __launch_bounds__(256)
void gemm_i8(const int8_t* __restrict__ Aq, const int8_t* __restrict__ Bq,
             const float* __restrict__ bias, float* __restrict__ C,
             int M, int N, int K, float S)
{
    extern __shared__ char smc[];

    const int tid  = threadIdx.x;
    const int w    = tid >> 5;
    const int lane = tid & 31;
    const int wm   = w & 1;
    const int wn   = w >> 1;
    const int bm   = blockIdx.y * 128;
    const int bn   = blockIdx.x * 64;
    const int NC   = K >> 5;
    const size_t planeA = (size_t)M * K;
    const size_t planeB = (size_t)N * K;

    // load mapping
    const int rowA = tid >> 1, segA = (tid & 1) * 16;   // A: 16B per thread
    const int rowB = tid >> 2, segB = (tid & 3) * 8;    // B: 8B per thread

    typedef wmma::fragment<wmma::matrix_a, 16, 16, 16,
                           signed char, wmma::row_major> FragA;
    typedef wmma::fragment<wmma::matrix_b, 16, 16, 16,
                           signed char, wmma::col_major> FragB;

    wmma::fragment<wmma::accumulator, 16, 16, 16, int> g[4][4];
#pragma unroll
    for (int gr = 0; gr < 4; gr++)
#pragma unroll
        for (int mi = 0; mi < 4; mi++)
            wmma::fill_fragment(g[gr][mi], 0);

    uint4 la[4];
    uint2 lb[4];

    auto ldg_chunk = [&](int c) {
        const int k0 = c << 5;
        const size_t aoff = (size_t)(bm + rowA) * K + k0 + segA;
#pragma unroll
        for (int t = 0; t < 4; t++)
            la[t] = *(const uint4*)(Aq + t * planeA + aoff);
        if (!GUARD || (bn + rowB) < N) {
            const size_t boff = (size_t)(bn + rowB) * K + k0 + segB;
#pragma unroll
            for (int t = 0; t < 4; t++)
                lb[t] = *(const uint2*)(Bq + t * planeB + boff);
        } else {
#pragma unroll
            for (int t = 0; t < 4; t++)
                lb[t] = make_uint2(0u, 0u);
        }
    };
    auto sts_chunk = [&](char* st) {
#pragma unroll
        for (int t = 0; t < 4; t++)
            *(uint4*)(st + t * ATILE + rowA * LDQ + segA) = la[t];
#pragma unroll
        for (int t = 0; t < 4; t++)
            *(uint2*)(st + 4 * ATILE + t * BTILE + rowB * LDQ + segB) = lb[t];
    };

    ldg_chunk(0);
    sts_chunk(smc);
    __syncthreads();

    for (int c = 0; c < NC; c++) {
        const int s = c & 1;
        if (c + 1 < NC) ldg_chunk(c + 1);

        const char* base = smc + s * STAGE;
#pragma unroll
        for (int k = 0; k < 2; k++) {
            FragB bf[4];
#pragma unroll
            for (int bi = 0; bi < 4; bi++)
                wmma::load_matrix_sync(bf[bi],
                    (const signed char*)(base + 4 * ATILE + bi * BTILE
                                         + (wn * 16) * LDQ + k * 16), LDQ);
#pragma unroll
            for (int al = 0; al < 4; al++) {
                FragA af[4];
#pragma unroll
                for (int mi = 0; mi < 4; mi++)
                    wmma::load_matrix_sync(af[mi],
                        (const signed char*)(base + al * ATILE
                             + (wm * 64 + mi * 16) * LDQ + k * 16), LDQ);
#pragma unroll
                for (int bi = 0; bi < 4; bi++) {
                    if (al + bi > 3) continue;   // keep only weight >= 2^-21
#pragma unroll
                    for (int mi = 0; mi < 4; mi++)
                        wmma::mma_sync(g[al + bi][mi], af[mi], bf[bi],
                                       g[al + bi][mi]);
                }
            }
        }

        if (c + 1 < NC) sts_chunk(smc + (s ^ 1) * STAGE);
        __syncthreads();
    }

    // epilogue: combine 4 groups with weights 1, 2^-7, 2^-14, 2^-21; x S
    float* scr = (float*)smc + w * 1024;    // 64x16 floats per warp
    const float c7 = 0.0078125f;
#pragma unroll
    for (int mi = 0; mi < 4; mi++) {
        wmma::fragment<wmma::accumulator, 16, 16, 16, float> f;
#pragma unroll
        for (int e = 0; e < f.num_elements; e++) {
            float v = (float)g[3][mi].x[e];
            v = fmaf(v, c7, (float)g[2][mi].x[e]);
            v = fmaf(v, c7, (float)g[1][mi].x[e]);
            v = fmaf(v, c7, (float)g[0][mi].x[e]);
            f.x[e] = v * S;
        }
        wmma::store_matrix_sync(scr + mi * 256, f, 16, wmma::mem_row_major);
    }
    __syncwarp();

    const int row0 = bm + wm * 64;
    const int col0 = bn + wn * 16;
    if (!GUARD || col0 < N) {
#pragma unroll
        for (int i = 0; i < 8; i++) {
            int idx = i * 32 + lane;        // 0..255 float4 slots
            int r   = idx >> 2;
            int cc  = (idx & 3) * 4;
            float4 v = *(float4*)(scr + r * 16 + cc);
            const float* bp = bias + col0 + cc;
            v.x += bp[0]; v.y += bp[1]; v.z += bp[2]; v.w += bp[3];
            if (RELU) {
                v.x = fmaxf(v.x, 0.f); v.y = fmaxf(v.y, 0.f);
                v.z = fmaxf(v.z, 0.f); v.w = fmaxf(v.w, 0.f);
            }
            *(float4*)(C + (size_t)(row0 + r) * N + col0 + cc) = v;
        }
    }
}

// ---------------------------------------------------------------------------
// Wavelet synthesis (recurrence-based, SMEM swizzled) — unchanged.
// ---------------------------------------------------------------------------
#define SYNTH_SMEM (8 * 2048 * 4 + 8 * 32 * 6 * 4 + 8 * 32 * 3 * 8)

__global__ __launch_bounds__(128)
void synth_kernel(const float* __restrict__ P, float* __restrict__ out)
{
    extern __shared__ float sms[];
    float*  acc = sms;
    float*  fp  = sms + 8 * 2048;
    double* dp  = (double*)(fp + 8 * 32 * 6);

    const int tid = threadIdx.x;
    const int b0  = blockIdx.x * 8;

    float4 z4 = make_float4(0.f, 0.f, 0.f, 0.f);
#pragma unroll
    for (int i = tid; i < 8 * 2048 / 4; i += 128)
        ((float4*)acc)[i] = z4;

    for (int p = tid; p < 8 * 32; p += 128) {
        int bl = p >> 5, n = p & 31;
        const float* q = P + (size_t)(b0 + bl) * 160 + n * 5;
        float  a  = q[0];
        double t0 = (1.0 / (1.0 + exp(-(double)q[1]))) * 2048.0;
        double fd = (1.0 / (1.0 + exp(-(double)q[2]))) * 0.5;
        double wd = 6.283185307179586 * fd;
        double sg = (1.0 / (1.0 + exp(-(double)q[3]))) * 200.0 + 2.0;
        double i2 = 1.0 / (2.0 * sg * sg);
        float* f6 = fp + p * 6;
        f6[0] = a;
        f6[1] = (float)i2;
        f6[2] = (float)cos(wd);
        f6[3] = (float)sin(wd);
        f6[4] = (float)exp(-2.0 * i2);
        f6[5] = (float)t0;
        double* d3 = dp + p * 3;
        d3[0] = t0; d3[1] = wd; d3[2] = (double)q[4];
    }
    __syncthreads();

    const int bl  = tid >> 4;
    const int tl  = tid & 15;
    const int col = tid;
    const int   sI = tl * 128;
    const float lo = (float)sI;
    const float hi = lo + 127.f;

    for (int n = 0; n < 32; n++) {
        const float* f6 = fp + (bl * 32 + n) * 6;
        float A = f6[0], i2 = f6[1], cw = f6[2], sw = f6[3], r = f6[4], t0f = f6[5];

        float dn = fmaxf(fmaxf(lo - t0f, t0f - hi), 0.f);
        if (dn * dn * i2 > 18.f) continue;

        float dfar = fmaxf(fabsf(lo - t0f), fabsf(hi - t0f));
        const double* d3 = dp + (bl * 32 + n) * 3;
        double t0d = d3[0], wd = d3[1], phid = d3[2];
        double dtd = (double)sI - t0d;

        if (dfar * dfar * i2 < 55.f) {
            double i2d = (double)i2;
            float g = A * __expf((float)(-dtd * dtd * i2d));
            float u = __expf((float)(-i2d * (2.0 * dtd + 1.0)));
            double ph = fma(wd, dtd, phid);
            double kq = rint(ph * 0.15915494309189535);
            float phr = (float)(ph - kq * 6.283185307179586);
            float c, s;
            __sincosf(phr, &s, &c);
#pragma unroll 4
            for (int i = 0; i < 128; i++) {
                int idx = i * 128 + ((col + i) & 127);
                acc[idx] += g * c;
                float cn  = fmaf(c, cw, -s * sw);
                float snn = fmaf(s, cw,  c * sw);
                c = cn; s = snn;
                g *= u;
                u *= r;
            }
        } else {
            for (int i = 0; i < 128; i++) {
                double dd = dtd + (double)i;
                float dt = (float)dd;
                float e = -dt * dt * i2;
                if (e > -18.f) {
                    double ph = fma(wd, dd, phid);
                    double kq = rint(ph * 0.15915494309189535);
                    float phr = (float)(ph - kq * 6.283185307179586);
                    int idx = i * 128 + ((col + i) & 127);
                    acc[idx] += A * __expf(e) * __cosf(phr);
                }
            }
        }
    }
    __syncthreads();

    for (int e = tid; e < 8 * 2048 / 4; e += 128) {
        int bl2 = e >> 9;
        int t   = (e & 511) * 4;
        int i0  = t & 127;
        int cb  = bl2 * 16 + (t >> 7);
        float4 v;
        v.x = acc[(i0 + 0) * 128 + ((cb + i0 + 0) & 127)];
        v.y = acc[(i0 + 1) * 128 + ((cb + i0 + 1) & 127)];
        v.z = acc[(i0 + 2) * 128 + ((cb + i0 + 2) & 127)];
        v.w = acc[(i0 + 3) * 128 + ((cb + i0 + 3) & 127)];
        size_t ob = ((size_t)(b0 + bl2) * 2) * 2048 + t;
        *(float4*)(out + ob)        = v;
        *(float4*)(out + ob + 2048) = v;
    }
}

// ---------------------------------------------------------------------------
extern "C" void kernel_launch(void* const* d_in, const int* in_sizes, int n_in,
                              void* d_out, int out_size)
{
    const float* x  = (const float*)d_in[0];
    const float* W1 = (const float*)d_in[1];
    const float* b1 = (const float*)d_in[2];
    const float* W2 = (const float*)d_in[3];
    const float* b2 = (const float*)d_in[4];
    const float* W3 = (const float*)d_in[5];
    const float* b3 = (const float*)d_in[6];
    const float* W4 = (const float*)d_in[7];
    const float* b4 = (const float*)d_in[8];
    float* out = (float*)d_out;

    float *h1, *h2, *h3, *pp;
    cudaGetSymbolAddress((void**)&h1, g_h1);
    cudaGetSymbolAddress((void**)&h2, g_h2);
    cudaGetSymbolAddress((void**)&h3, g_h3);
    cudaGetSymbolAddress((void**)&pp, g_p);

    int8_t *xq, *h1q, *h2q, *h3q, *w1q, *w2q, *w3q, *w4q;
    cudaGetSymbolAddress((void**)&xq,  g_xq);
    cudaGetSymbolAddress((void**)&h1q, g_h1q);
    cudaGetSymbolAddress((void**)&h2q, g_h2q);
    cudaGetSymbolAddress((void**)&h3q, g_h3q);
    cudaGetSymbolAddress((void**)&w1q, g_w1q);
    cudaGetSymbolAddress((void**)&w2q, g_w2q);
    cudaGetSymbolAddress((void**)&w3q, g_w3q);
    cudaGetSymbolAddress((void**)&w4q, g_w4q);

    cudaFuncSetAttribute(gemm_i8<true, false>,
                         cudaFuncAttributeMaxDynamicSharedMemorySize, GEMM_SMEM);
    cudaFuncSetAttribute(gemm_i8<false, true>,
                         cudaFuncAttributeMaxDynamicSharedMemorySize, GEMM_SMEM);
    cudaFuncSetAttribute(synth_kernel,
                         cudaFuncAttributeMaxDynamicSharedMemorySize, SYNTH_SMEM);

    auto quant = [&](const float* s, int8_t* d, float invS, size_t n) {
        int n4 = (int)(n / 4);
        quant_kernel<<<(n4 + 255) / 256, 256>>>(s, d, invS, n4, n);
    };

    // scales: activations sA = 16 (x), 32 (h); weights sB = 0.25 (W1,W2), 0.5 (W3,W4)
    // S = sA * sB * 2^-14
    quant(x,  xq,  0.0625f, 4096ull * 4096);
    quant(W1, w1q, 4.0f,    1024ull * 4096);
    gemm_i8<true, false><<<dim3(16, 32), 256, GEMM_SMEM>>>(
        xq, w1q, b1, h1, 4096, 1024, 4096, 16.f * 0.25f / 16384.f);

    quant(h1, h1q, 0.03125f, 4096ull * 1024);
    quant(W2, w2q, 4.0f,     512ull * 1024);
    gemm_i8<true, false><<<dim3(8, 32), 256, GEMM_SMEM>>>(
        h1q, w2q, b2, h2, 4096, 512, 1024, 32.f * 0.25f / 16384.f);

    quant(h2, h2q, 0.03125f, 4096ull * 512);
    quant(W3, w3q, 2.0f,     256ull * 512);
    gemm_i8<true, false><<<dim3(4, 32), 256, GEMM_SMEM>>>(
        h2q, w3q, b3, h3, 4096, 256, 512, 32.f * 0.5f / 16384.f);

    quant(h3, h3q, 0.03125f, 4096ull * 256);
    quant(W4, w4q, 2.0f,     160ull * 256);
    gemm_i8<false, true><<<dim3(3, 32), 256, GEMM_SMEM>>>(
        h3q, w4q, b4, pp, 4096, 160, 256, 32.f * 0.5f / 16384.f);

    synth_kernel<<<4096 / 8, 128, SYNTH_SMEM>>>(pp, out);
}

// round 7
// speedup vs baseline: 3.0296x; 3.0296x over previous
#include <cuda_runtime.h>
#include <math.h>
#include <cstdint>

// ---------------------------------------------------------------------------
// GaborAutoencoder: encoder via SIMT fp32 GEMM using packed fp32x2 FMA
// (fma.rn.f32x2 -> FFMA2, 2x FFMA throughput, exact fp32) -> synthesis.
// All MMA paths exhausted: tcgen05 blocked by sm_103 base target; legacy
// FP-MMA has a rounding accumulator (R3-R5); legacy I-MMA emulated ~FFMA
// rate (R6, 6.6ms). FFMA2 doubles the SIMT fp32 roof instead.
// ---------------------------------------------------------------------------

__device__ float g_h1[4096 * 1024];
__device__ float g_h2[4096 * 512];
__device__ float g_h3[4096 * 256];
__device__ float g_p [4096 * 160];

typedef unsigned long long u64;

__device__ __forceinline__ void ffma2(u64& d, u64 a, u64 b) {
    asm("fma.rn.f32x2 %0, %1, %2, %0;" : "+l"(d) : "l"(a), "l"(b));
}
__device__ __forceinline__ u64 dup2(float x) {
    u64 r;
    asm("mov.b64 %0, {%1, %1};" : "=l"(r) : "f"(x));
    return r;
}

// ---------------------------------------------------------------------------
// GEMM: C[m,n] = act( sum_k A[m,k]*W[n,k] + bias[n] )
// A: MxK row-major, W: NxK row-major. BM=BN=128, BK=32, 256 threads.
// Thread tile 8(M) x 8(N) as 8 rows x 4 f32x2 column-pairs.
// SMEM tiles [k][row] (transposed on store), padded to 132 floats/row.
// ---------------------------------------------------------------------------
#define LDSA 132
#define TILE_FL (32 * LDSA)                // 4224 floats
#define STAGE_FL (2 * TILE_FL)
#define GEMM_SMEM (2 * STAGE_FL * 4)       // 67584 bytes

template<bool RELU, bool GUARD>
__global__ __launch_bounds__(256)
void gemm_f32x2(const float* __restrict__ A, const float* __restrict__ W,
                const float* __restrict__ bias, float* __restrict__ C,
                int M, int N, int K)
{
    extern __shared__ float sm[];

    const int tid = threadIdx.x;
    const int tr  = tid >> 4;              // 0..15: row group
    const int tc  = tid & 15;              // 0..15: col group
    const int bm  = blockIdx.y * 128;
    const int bn  = blockIdx.x * 128;
    const int NC  = K >> 5;

    // load mapping: 1024 float4 per tile, 4 per thread
    const int lrow[4] = { (0*256 + tid) >> 3, (1*256 + tid) >> 3,
                          (2*256 + tid) >> 3, (3*256 + tid) >> 3 };
    const int lk = (tid & 7) * 4;

    u64 acc[8][4];
#pragma unroll
    for (int i = 0; i < 8; i++)
#pragma unroll
        for (int j = 0; j < 4; j++) acc[i][j] = 0ull;

    float4 rA[4], rW[4];

    auto ldg_chunk = [&](int c) {
        const int k0 = c << 5;
#pragma unroll
        for (int it = 0; it < 4; it++) {
            rA[it] = *(const float4*)(A + (size_t)(bm + lrow[it]) * K + k0 + lk);
            float4 v = make_float4(0.f, 0.f, 0.f, 0.f);
            if (!GUARD || (bn + lrow[it]) < N)
                v = *(const float4*)(W + (size_t)(bn + lrow[it]) * K + k0 + lk);
            rW[it] = v;
        }
    };
    auto sts_chunk = [&](float* st) {
        float* sa = st;
        float* sb = st + TILE_FL;
#pragma unroll
        for (int it = 0; it < 4; it++) {
            float4 a = rA[it], b = rW[it];
            sa[(lk + 0) * LDSA + lrow[it]] = a.x;
            sa[(lk + 1) * LDSA + lrow[it]] = a.y;
            sa[(lk + 2) * LDSA + lrow[it]] = a.z;
            sa[(lk + 3) * LDSA + lrow[it]] = a.w;
            sb[(lk + 0) * LDSA + lrow[it]] = b.x;
            sb[(lk + 1) * LDSA + lrow[it]] = b.y;
            sb[(lk + 2) * LDSA + lrow[it]] = b.z;
            sb[(lk + 3) * LDSA + lrow[it]] = b.w;
        }
    };

    ldg_chunk(0);
    sts_chunk(sm);
    __syncthreads();

    for (int c = 0; c < NC; c++) {
        const int s = c & 1;
        if (c + 1 < NC) ldg_chunk(c + 1);

        const float* sa = sm + s * STAGE_FL + tr * 8;
        const float* sb = sm + s * STAGE_FL + TILE_FL + tc * 8;

#pragma unroll 8
        for (int k = 0; k < 32; k++) {
            float4 a0 = *(const float4*)(sa + k * LDSA);
            float4 a1 = *(const float4*)(sa + k * LDSA + 4);
            // natural column pairs as 64-bit lanes
            ulonglong2 bp0 = *(const ulonglong2*)(sb + k * LDSA);
            ulonglong2 bp1 = *(const ulonglong2*)(sb + k * LDSA + 4);
            u64 bq[4] = { bp0.x, bp0.y, bp1.x, bp1.y };
            u64 ad[8] = { dup2(a0.x), dup2(a0.y), dup2(a0.z), dup2(a0.w),
                          dup2(a1.x), dup2(a1.y), dup2(a1.z), dup2(a1.w) };
#pragma unroll
            for (int i = 0; i < 8; i++)
#pragma unroll
                for (int j = 0; j < 4; j++)
                    ffma2(acc[i][j], ad[i], bq[j]);
        }

        if (c + 1 < NC) sts_chunk(sm + (s ^ 1) * STAGE_FL);
        __syncthreads();
    }

    // epilogue
    const int col0 = bn + tc * 8;
    if (!GUARD || col0 < N) {                 // per-thread cols all-or-nothing
        float bv[8];
#pragma unroll
        for (int j = 0; j < 8; j += 4) {
            float4 b4 = *(const float4*)(bias + col0 + j);
            bv[j] = b4.x; bv[j + 1] = b4.y; bv[j + 2] = b4.z; bv[j + 3] = b4.w;
        }
#pragma unroll
        for (int i = 0; i < 8; i++) {
            float o[8];
#pragma unroll
            for (int j = 0; j < 4; j++) {
                o[2 * j]     = __uint_as_float((unsigned)(acc[i][j] & 0xFFFFFFFFull));
                o[2 * j + 1] = __uint_as_float((unsigned)(acc[i][j] >> 32));
            }
#pragma unroll
            for (int j = 0; j < 8; j++) {
                o[j] += bv[j];
                if (RELU) o[j] = fmaxf(o[j], 0.f);
            }
            float* crow = C + (size_t)(bm + tr * 8 + i) * N + col0;
            *(float4*)(crow)     = make_float4(o[0], o[1], o[2], o[3]);
            *(float4*)(crow + 4) = make_float4(o[4], o[5], o[6], o[7]);
        }
    }
}

// ---------------------------------------------------------------------------
// Wavelet synthesis (recurrence-based, SMEM swizzled) — unchanged.
// ---------------------------------------------------------------------------
#define SYNTH_SMEM (8 * 2048 * 4 + 8 * 32 * 6 * 4 + 8 * 32 * 3 * 8)

__global__ __launch_bounds__(128)
void synth_kernel(const float* __restrict__ P, float* __restrict__ out)
{
    extern __shared__ float sms[];
    float*  acc = sms;
    float*  fp  = sms + 8 * 2048;
    double* dp  = (double*)(fp + 8 * 32 * 6);

    const int tid = threadIdx.x;
    const int b0  = blockIdx.x * 8;

    float4 z4 = make_float4(0.f, 0.f, 0.f, 0.f);
#pragma unroll
    for (int i = tid; i < 8 * 2048 / 4; i += 128)
        ((float4*)acc)[i] = z4;

    for (int p = tid; p < 8 * 32; p += 128) {
        int bl = p >> 5, n = p & 31;
        const float* q = P + (size_t)(b0 + bl) * 160 + n * 5;
        float  a  = q[0];
        double t0 = (1.0 / (1.0 + exp(-(double)q[1]))) * 2048.0;
        double fd = (1.0 / (1.0 + exp(-(double)q[2]))) * 0.5;
        double wd = 6.283185307179586 * fd;
        double sg = (1.0 / (1.0 + exp(-(double)q[3]))) * 200.0 + 2.0;
        double i2 = 1.0 / (2.0 * sg * sg);
        float* f6 = fp + p * 6;
        f6[0] = a;
        f6[1] = (float)i2;
        f6[2] = (float)cos(wd);
        f6[3] = (float)sin(wd);
        f6[4] = (float)exp(-2.0 * i2);
        f6[5] = (float)t0;
        double* d3 = dp + p * 3;
        d3[0] = t0; d3[1] = wd; d3[2] = (double)q[4];
    }
    __syncthreads();

    const int bl  = tid >> 4;
    const int tl  = tid & 15;
    const int col = tid;
    const int   sI = tl * 128;
    const float lo = (float)sI;
    const float hi = lo + 127.f;

    for (int n = 0; n < 32; n++) {
        const float* f6 = fp + (bl * 32 + n) * 6;
        float A = f6[0], i2 = f6[1], cw = f6[2], sw = f6[3], r = f6[4], t0f = f6[5];

        float dn = fmaxf(fmaxf(lo - t0f, t0f - hi), 0.f);
        if (dn * dn * i2 > 18.f) continue;

        float dfar = fmaxf(fabsf(lo - t0f), fabsf(hi - t0f));
        const double* d3 = dp + (bl * 32 + n) * 3;
        double t0d = d3[0], wd = d3[1], phid = d3[2];
        double dtd = (double)sI - t0d;

        if (dfar * dfar * i2 < 55.f) {
            double i2d = (double)i2;
            float g = A * __expf((float)(-dtd * dtd * i2d));
            float u = __expf((float)(-i2d * (2.0 * dtd + 1.0)));
            double ph = fma(wd, dtd, phid);
            double kq = rint(ph * 0.15915494309189535);
            float phr = (float)(ph - kq * 6.283185307179586);
            float c, s;
            __sincosf(phr, &s, &c);
#pragma unroll 4
            for (int i = 0; i < 128; i++) {
                int idx = i * 128 + ((col + i) & 127);
                acc[idx] += g * c;
                float cn  = fmaf(c, cw, -s * sw);
                float snn = fmaf(s, cw,  c * sw);
                c = cn; s = snn;
                g *= u;
                u *= r;
            }
        } else {
            for (int i = 0; i < 128; i++) {
                double dd = dtd + (double)i;
                float dt = (float)dd;
                float e = -dt * dt * i2;
                if (e > -18.f) {
                    double ph = fma(wd, dd, phid);
                    double kq = rint(ph * 0.15915494309189535);
                    float phr = (float)(ph - kq * 6.283185307179586);
                    int idx = i * 128 + ((col + i) & 127);
                    acc[idx] += A * __expf(e) * __cosf(phr);
                }
            }
        }
    }
    __syncthreads();

    for (int e = tid; e < 8 * 2048 / 4; e += 128) {
        int bl2 = e >> 9;
        int t   = (e & 511) * 4;
        int i0  = t & 127;
        int cb  = bl2 * 16 + (t >> 7);
        float4 v;
        v.x = acc[(i0 + 0) * 128 + ((cb + i0 + 0) & 127)];
        v.y = acc[(i0 + 1) * 128 + ((cb + i0 + 1) & 127)];
        v.z = acc[(i0 + 2) * 128 + ((cb + i0 + 2) & 127)];
        v.w = acc[(i0 + 3) * 128 + ((cb + i0 + 3) & 127)];
        size_t ob = ((size_t)(b0 + bl2) * 2) * 2048 + t;
        *(float4*)(out + ob)        = v;
        *(float4*)(out + ob + 2048) = v;
    }
}

// ---------------------------------------------------------------------------
extern "C" void kernel_launch(void* const* d_in, const int* in_sizes, int n_in,
                              void* d_out, int out_size)
{
    const float* x  = (const float*)d_in[0];
    const float* W1 = (const float*)d_in[1];
    const float* b1 = (const float*)d_in[2];
    const float* W2 = (const float*)d_in[3];
    const float* b2 = (const float*)d_in[4];
    const float* W3 = (const float*)d_in[5];
    const float* b3 = (const float*)d_in[6];
    const float* W4 = (const float*)d_in[7];
    const float* b4 = (const float*)d_in[8];
    float* out = (float*)d_out;

    float *h1, *h2, *h3, *pp;
    cudaGetSymbolAddress((void**)&h1, g_h1);
    cudaGetSymbolAddress((void**)&h2, g_h2);
    cudaGetSymbolAddress((void**)&h3, g_h3);
    cudaGetSymbolAddress((void**)&pp, g_p);

    cudaFuncSetAttribute(gemm_f32x2<true, false>,
                         cudaFuncAttributeMaxDynamicSharedMemorySize, GEMM_SMEM);
    cudaFuncSetAttribute(gemm_f32x2<false, true>,
                         cudaFuncAttributeMaxDynamicSharedMemorySize, GEMM_SMEM);
    cudaFuncSetAttribute(synth_kernel,
                         cudaFuncAttributeMaxDynamicSharedMemorySize, SYNTH_SMEM);

    gemm_f32x2<true, false><<<dim3(8, 32), 256, GEMM_SMEM>>>(
        x, W1, b1, h1, 4096, 1024, 4096);
    gemm_f32x2<true, false><<<dim3(4, 32), 256, GEMM_SMEM>>>(
        h1, W2, b2, h2, 4096, 512, 1024);
    gemm_f32x2<true, false><<<dim3(2, 32), 256, GEMM_SMEM>>>(
        h2, W3, b3, h3, 4096, 256, 512);
    gemm_f32x2<false, true><<<dim3(2, 32), 256, GEMM_SMEM>>>(
        h3, W4, b4, pp, 4096, 160, 256);

    synth_kernel<<<4096 / 8, 128, SYNTH_SMEM>>>(pp, out);
}

// round 9
// speedup vs baseline: 5.1377x; 1.6959x over previous
#include <cuda_runtime.h>
#include <math.h>
#include <cstdint>

// ---------------------------------------------------------------------------
// GaborAutoencoder: encoder = pipelined SIMT fp32 GEMM (fma.rn.f32x2
// formulation; exact fp32 either way) -> wavelet synthesis.
// Tensor paths dead on this toolchain: tcgen05 rejected (PTX targets sm_103
// base), legacy FP-MMA accumulator rounds (R3-R5), legacy I-MMA emulated at
// ~FFMA rate (R6). This round: hide LDS latency with register-pipelined
// fragments; per-layer BN for full-grid occupancy on small layers.
// ---------------------------------------------------------------------------

__device__ float g_h1[4096 * 1024];
__device__ float g_h2[4096 * 512];
__device__ float g_h3[4096 * 256];
__device__ float g_p [4096 * 160];

typedef unsigned long long u64;

__device__ __forceinline__ void ffma2(u64& d, u64 a, u64 b) {
    asm("fma.rn.f32x2 %0, %1, %2, %0;" : "+l"(d) : "l"(a), "l"(b));
}
__device__ __forceinline__ u64 dup2(float x) {
    u64 r;
    asm("mov.b64 %0, {%1, %1};" : "=l"(r) : "f"(x));
    return r;
}

// ---------------------------------------------------------------------------
// GEMM: C[m,n] = act( sum_k A[m,k]*W[n,k] + bias[n] )
// A: MxK row-major, W: NxK row-major (both K contiguous). BM=128 fixed,
// BK=16, 256 threads as 16x16; thread tile 8 x TN, TN = BN/16.
// SMEM transposed tiles [k][row], double buffered; register-pipelined frags.
// All layer dims divide the tiles (N4=160=5*32) -> no guards anywhere.
// ---------------------------------------------------------------------------
#define BKC 16
#define LDA_S 132

template<int BN, bool RELU>
__global__ __launch_bounds__(256, 2)
void gemm_v3(const float* __restrict__ A, const float* __restrict__ W,
             const float* __restrict__ bias, float* __restrict__ C,
             int M, int N, int K)
{
    constexpr int TN = BN / 16;
    constexpr int NP = TN / 2;
    constexpr int LDB_S = BN + 4;
    constexpr int ATILE_F = BKC * LDA_S;
    constexpr int BTILE_F = BKC * LDB_S;
    constexpr int STAGE_F = ATILE_F + BTILE_F;
    constexpr int BB4 = BN * BKC / 4;            // B float4 count
    constexpr int NB_IT = (BB4 + 255) / 256;

    extern __shared__ float sm[];

    const int tid = threadIdx.x;
    const int tr  = tid >> 4;
    const int tc  = tid & 15;
    const int bm  = blockIdx.y * 128;
    const int bn  = blockIdx.x * BN;
    const int NCk = K / BKC;

    const int lrow = tid >> 2;                   // + it*64
    const int lk   = (tid & 3) * 4;

    u64 acc[8][NP];
#pragma unroll
    for (int i = 0; i < 8; i++)
#pragma unroll
        for (int j = 0; j < NP; j++) acc[i][j] = 0ull;

    float4 rA[2], rB[NB_IT];

    auto ldg = [&](int c) {
        const int k0 = c * BKC;
#pragma unroll
        for (int it = 0; it < 2; it++)
            rA[it] = *(const float4*)(A + (size_t)(bm + it * 64 + lrow) * K + k0 + lk);
#pragma unroll
        for (int it = 0; it < NB_IT; it++) {
            int idx = it * 256 + tid;
            if ((BB4 % 256 == 0) || idx < BB4)
                rB[it] = *(const float4*)(W + (size_t)(bn + (idx >> 2)) * K + k0 + lk);
        }
    };
    auto sts = [&](float* st) {
        float* sa = st;
        float* sb = st + ATILE_F;
#pragma unroll
        for (int it = 0; it < 2; it++) {
            float4 v = rA[it];
            int row = it * 64 + lrow;
            sa[(lk + 0) * LDA_S + row] = v.x;
            sa[(lk + 1) * LDA_S + row] = v.y;
            sa[(lk + 2) * LDA_S + row] = v.z;
            sa[(lk + 3) * LDA_S + row] = v.w;
        }
#pragma unroll
        for (int it = 0; it < NB_IT; it++) {
            int idx = it * 256 + tid;
            if ((BB4 % 256 == 0) || idx < BB4) {
                float4 v = rB[it];
                int row = idx >> 2;
                sb[(lk + 0) * LDB_S + row] = v.x;
                sb[(lk + 1) * LDB_S + row] = v.y;
                sb[(lk + 2) * LDB_S + row] = v.z;
                sb[(lk + 3) * LDB_S + row] = v.w;
            }
        }
    };

    ldg(0);
    sts(sm);
    __syncthreads();

    for (int c = 0; c < NCk; c++) {
        const int s = c & 1;
        if (c + 1 < NCk) ldg(c + 1);

        const float* sa = sm + s * STAGE_F + tr * 8;
        const float* sb = sm + s * STAGE_F + ATILE_F + tc * TN;

        float fa[2][8];
        u64   fb[2][NP];
        // prefetch k=0
        {
            float4 a0 = *(const float4*)(sa);
            float4 a1 = *(const float4*)(sa + 4);
            fa[0][0] = a0.x; fa[0][1] = a0.y; fa[0][2] = a0.z; fa[0][3] = a0.w;
            fa[0][4] = a1.x; fa[0][5] = a1.y; fa[0][6] = a1.z; fa[0][7] = a1.w;
#pragma unroll
            for (int j = 0; j < NP; j++)
                fb[0][j] = *(const u64*)(sb + 2 * j);
        }
#pragma unroll
        for (int k = 0; k < BKC; k++) {
            const int cur = k & 1;
            if (k + 1 < BKC) {
                const float* sak = sa + (k + 1) * LDA_S;
                const float* sbk = sb + (k + 1) * LDB_S;
                float4 a0 = *(const float4*)(sak);
                float4 a1 = *(const float4*)(sak + 4);
                fa[cur ^ 1][0] = a0.x; fa[cur ^ 1][1] = a0.y;
                fa[cur ^ 1][2] = a0.z; fa[cur ^ 1][3] = a0.w;
                fa[cur ^ 1][4] = a1.x; fa[cur ^ 1][5] = a1.y;
                fa[cur ^ 1][6] = a1.z; fa[cur ^ 1][7] = a1.w;
#pragma unroll
                for (int j = 0; j < NP; j++)
                    fb[cur ^ 1][j] = *(const u64*)(sbk + 2 * j);
            }
#pragma unroll
            for (int i = 0; i < 8; i++) {
                u64 ad = dup2(fa[cur][i]);
#pragma unroll
                for (int j = 0; j < NP; j++)
                    ffma2(acc[i][j], ad, fb[cur][j]);
            }
        }

        if (c + 1 < NCk) sts(sm + (s ^ 1) * STAGE_F);
        __syncthreads();
    }

    // epilogue (no guards: all layer dims divide the tile sizes)
    const int col0 = bn + tc * TN;
    float bv[TN];
#pragma unroll
    for (int j = 0; j < TN; j++) bv[j] = bias[col0 + j];
#pragma unroll
    for (int i = 0; i < 8; i++) {
        float* crow = C + (size_t)(bm + tr * 8 + i) * N + col0;
#pragma unroll
        for (int j = 0; j < NP; j++) {
            float2 o;
            o.x = __uint_as_float((unsigned)(acc[i][j] & 0xFFFFFFFFull)) + bv[2 * j];
            o.y = __uint_as_float((unsigned)(acc[i][j] >> 32)) + bv[2 * j + 1];
            if (RELU) { o.x = fmaxf(o.x, 0.f); o.y = fmaxf(o.y, 0.f); }
            *(float2*)(crow + 2 * j) = o;
        }
    }
}

// ---------------------------------------------------------------------------
// Wavelet synthesis (recurrence-based, SMEM swizzled) — unchanged.
// ---------------------------------------------------------------------------
#define SYNTH_SMEM (8 * 2048 * 4 + 8 * 32 * 6 * 4 + 8 * 32 * 3 * 8)

__global__ __launch_bounds__(128)
void synth_kernel(const float* __restrict__ P, float* __restrict__ out)
{
    extern __shared__ float sms[];
    float*  acc = sms;
    float*  fp  = sms + 8 * 2048;
    double* dp  = (double*)(fp + 8 * 32 * 6);

    const int tid = threadIdx.x;
    const int b0  = blockIdx.x * 8;

    float4 z4 = make_float4(0.f, 0.f, 0.f, 0.f);
#pragma unroll
    for (int i = tid; i < 8 * 2048 / 4; i += 128)
        ((float4*)acc)[i] = z4;

    for (int p = tid; p < 8 * 32; p += 128) {
        int bl = p >> 5, n = p & 31;
        const float* q = P + (size_t)(b0 + bl) * 160 + n * 5;
        float  a  = q[0];
        double t0 = (1.0 / (1.0 + exp(-(double)q[1]))) * 2048.0;
        double fd = (1.0 / (1.0 + exp(-(double)q[2]))) * 0.5;
        double wd = 6.283185307179586 * fd;
        double sg = (1.0 / (1.0 + exp(-(double)q[3]))) * 200.0 + 2.0;
        double i2 = 1.0 / (2.0 * sg * sg);
        float* f6 = fp + p * 6;
        f6[0] = a;
        f6[1] = (float)i2;
        f6[2] = (float)cos(wd);
        f6[3] = (float)sin(wd);
        f6[4] = (float)exp(-2.0 * i2);
        f6[5] = (float)t0;
        double* d3 = dp + p * 3;
        d3[0] = t0; d3[1] = wd; d3[2] = (double)q[4];
    }
    __syncthreads();

    const int bl  = tid >> 4;
    const int tl  = tid & 15;
    const int col = tid;
    const int   sI = tl * 128;
    const float lo = (float)sI;
    const float hi = lo + 127.f;

    for (int n = 0; n < 32; n++) {
        const float* f6 = fp + (bl * 32 + n) * 6;
        float A = f6[0], i2 = f6[1], cw = f6[2], sw = f6[3], r = f6[4], t0f = f6[5];

        float dn = fmaxf(fmaxf(lo - t0f, t0f - hi), 0.f);
        if (dn * dn * i2 > 18.f) continue;

        float dfar = fmaxf(fabsf(lo - t0f), fabsf(hi - t0f));
        const double* d3 = dp + (bl * 32 + n) * 3;
        double t0d = d3[0], wd = d3[1], phid = d3[2];
        double dtd = (double)sI - t0d;

        if (dfar * dfar * i2 < 55.f) {
            double i2d = (double)i2;
            float g = A * __expf((float)(-dtd * dtd * i2d));
            float u = __expf((float)(-i2d * (2.0 * dtd + 1.0)));
            double ph = fma(wd, dtd, phid);
            double kq = rint(ph * 0.15915494309189535);
            float phr = (float)(ph - kq * 6.283185307179586);
            float c, s;
            __sincosf(phr, &s, &c);
#pragma unroll 4
            for (int i = 0; i < 128; i++) {
                int idx = i * 128 + ((col + i) & 127);
                acc[idx] += g * c;
                float cn  = fmaf(c, cw, -s * sw);
                float snn = fmaf(s, cw,  c * sw);
                c = cn; s = snn;
                g *= u;
                u *= r;
            }
        } else {
            for (int i = 0; i < 128; i++) {
                double dd = dtd + (double)i;
                float dt = (float)dd;
                float e = -dt * dt * i2;
                if (e > -18.f) {
                    double ph = fma(wd, dd, phid);
                    double kq = rint(ph * 0.15915494309189535);
                    float phr = (float)(ph - kq * 6.283185307179586);
                    int idx = i * 128 + ((col + i) & 127);
                    acc[idx] += A * __expf(e) * __cosf(phr);
                }
            }
        }
    }
    __syncthreads();

    for (int e = tid; e < 8 * 2048 / 4; e += 128) {
        int bl2 = e >> 9;
        int t   = (e & 511) * 4;
        int i0  = t & 127;
        int cb  = bl2 * 16 + (t >> 7);
        float4 v;
        v.x = acc[(i0 + 0) * 128 + ((cb + i0 + 0) & 127)];
        v.y = acc[(i0 + 1) * 128 + ((cb + i0 + 1) & 127)];
        v.z = acc[(i0 + 2) * 128 + ((cb + i0 + 2) & 127)];
        v.w = acc[(i0 + 3) * 128 + ((cb + i0 + 3) & 127)];
        size_t ob = ((size_t)(b0 + bl2) * 2) * 2048 + t;
        *(float4*)(out + ob)        = v;
        *(float4*)(out + ob + 2048) = v;
    }
}

// ---------------------------------------------------------------------------
extern "C" void kernel_launch(void* const* d_in, const int* in_sizes, int n_in,
                              void* d_out, int out_size)
{
    const float* x  = (const float*)d_in[0];
    const float* W1 = (const float*)d_in[1];
    const float* b1 = (const float*)d_in[2];
    const float* W2 = (const float*)d_in[3];
    const float* b2 = (const float*)d_in[4];
    const float* W3 = (const float*)d_in[5];
    const float* b3 = (const float*)d_in[6];
    const float* W4 = (const float*)d_in[7];
    const float* b4 = (const float*)d_in[8];
    float* out = (float*)d_out;

    float *h1, *h2, *h3, *pp;
    cudaGetSymbolAddress((void**)&h1, g_h1);
    cudaGetSymbolAddress((void**)&h2, g_h2);
    cudaGetSymbolAddress((void**)&h3, g_h3);
    cudaGetSymbolAddress((void**)&pp, g_p);

    cudaFuncSetAttribute(synth_kernel,
                         cudaFuncAttributeMaxDynamicSharedMemorySize, SYNTH_SMEM);

    // SMEM: (16*132 + 16*(BN+4)) * 2 stages * 4B
    const int smem128 = (16 * 132 + 16 * 132) * 2 * 4;   // 33792
    const int smem64  = (16 * 132 + 16 * 68)  * 2 * 4;   // 25600
    const int smem32  = (16 * 132 + 16 * 36)  * 2 * 4;   // 21504

    gemm_v3<128, true><<<dim3(8, 32), 256, smem128>>>(
        x, W1, b1, h1, 4096, 1024, 4096);
    gemm_v3<128, true><<<dim3(4, 32), 256, smem128>>>(
        h1, W2, b2, h2, 4096, 512, 1024);
    gemm_v3<64, true><<<dim3(4, 32), 256, smem64>>>(
        h2, W3, b3, h3, 4096, 256, 512);
    gemm_v3<32, false><<<dim3(5, 32), 256, smem32>>>(
        h3, W4, b4, pp, 4096, 160, 256);

    synth_kernel<<<4096 / 8, 128, SYNTH_SMEM>>>(pp, out);
}

// round 10
// speedup vs baseline: 5.3261x; 1.0367x over previous
#include <cuda_runtime.h>
#include <math.h>
#include <cstdint>

// ---------------------------------------------------------------------------
// GaborAutoencoder: encoder = pipelined SIMT fp32 GEMM with packed FFMA2.
// R8 analysis: 8x8 tile = 1.0 B/MAC = exactly the 128 B/cyc smem crossbar at
// the 128 MAC/cyc FFMA2 rate -> co-limited. This round: 16x8 thread tile
// (0.75 B/MAC) for L1/L2 so the fma pipe is the sole limiter.
// ---------------------------------------------------------------------------

__device__ float g_h1[4096 * 1024];
__device__ float g_h2[4096 * 512];
__device__ float g_h3[4096 * 256];
__device__ float g_p [4096 * 160];

typedef unsigned long long u64;

__device__ __forceinline__ void ffma2(u64& d, u64 a, u64 b) {
    asm("fma.rn.f32x2 %0, %1, %2, %0;" : "+l"(d) : "l"(a), "l"(b));
}
__device__ __forceinline__ u64 dup2(float x) {
    u64 r;
    asm("mov.b64 %0, {%1, %1};" : "=l"(r) : "f"(x));
    return r;
}

#define BKC 16
#define LDA_S 132

// ---------------------------------------------------------------------------
// v4: 128 threads, BM=128, BN=128, thread tile 16(M) x 8(N). For L1/L2.
// ---------------------------------------------------------------------------
#define V4_ATILE (BKC * LDA_S)
#define V4_STAGE (2 * V4_ATILE)
#define V4_SMEM  (2 * V4_STAGE * 4)      // 33792 B

template<bool RELU>
__global__ __launch_bounds__(128, 2)
void gemm_v4(const float* __restrict__ A, const float* __restrict__ W,
             const float* __restrict__ bias, float* __restrict__ C,
             int M, int N, int K)
{
    extern __shared__ float sm[];

    const int tid = threadIdx.x;
    const int tr  = tid >> 4;            // 0..7  -> rows tr*16..+15
    const int tc  = tid & 15;            // 0..15 -> cols tc*8..+7
    const int bm  = blockIdx.y * 128;
    const int bn  = blockIdx.x * 128;
    const int NCk = K / BKC;

    // ldg mapping: 512 float4 per tile, 4 per thread
    const int lrow[4] = { (0*128 + tid) >> 2, (1*128 + tid) >> 2,
                          (2*128 + tid) >> 2, (3*128 + tid) >> 2 };
    const int lk = (tid & 3) * 4;

    u64 acc[16][4];
#pragma unroll
    for (int i = 0; i < 16; i++)
#pragma unroll
        for (int j = 0; j < 4; j++) acc[i][j] = 0ull;

    float4 rA[4], rB[4];

    auto ldg = [&](int c) {
        const int k0 = c * BKC;
#pragma unroll
        for (int it = 0; it < 4; it++) {
            rA[it] = *(const float4*)(A + (size_t)(bm + lrow[it]) * K + k0 + lk);
            rB[it] = *(const float4*)(W + (size_t)(bn + lrow[it]) * K + k0 + lk);
        }
    };
    auto sts = [&](float* st) {
        float* sa = st;
        float* sb = st + V4_ATILE;
#pragma unroll
        for (int it = 0; it < 4; it++) {
            float4 a = rA[it], b = rB[it];
            int row = lrow[it];
            sa[(lk + 0) * LDA_S + row] = a.x;
            sa[(lk + 1) * LDA_S + row] = a.y;
            sa[(lk + 2) * LDA_S + row] = a.z;
            sa[(lk + 3) * LDA_S + row] = a.w;
            sb[(lk + 0) * LDA_S + row] = b.x;
            sb[(lk + 1) * LDA_S + row] = b.y;
            sb[(lk + 2) * LDA_S + row] = b.z;
            sb[(lk + 3) * LDA_S + row] = b.w;
        }
    };

    ldg(0);
    sts(sm);
    __syncthreads();

    for (int c = 0; c < NCk; c++) {
        const int s = c & 1;
        if (c + 1 < NCk) ldg(c + 1);

        const float* sa = sm + s * V4_STAGE + tr * 16;
        const float* sb = sm + s * V4_STAGE + V4_ATILE + tc * 8;

        float fa[2][16];
        u64   fb[2][4];
        {
#pragma unroll
            for (int q = 0; q < 4; q++) {
                float4 v = *(const float4*)(sa + q * 4);
                fa[0][q * 4 + 0] = v.x; fa[0][q * 4 + 1] = v.y;
                fa[0][q * 4 + 2] = v.z; fa[0][q * 4 + 3] = v.w;
            }
            ulonglong2 b0 = *(const ulonglong2*)(sb);
            ulonglong2 b1 = *(const ulonglong2*)(sb + 4);
            fb[0][0] = b0.x; fb[0][1] = b0.y; fb[0][2] = b1.x; fb[0][3] = b1.y;
        }
#pragma unroll
        for (int k = 0; k < BKC; k++) {
            const int cur = k & 1;
            if (k + 1 < BKC) {
                const float* sak = sa + (k + 1) * LDA_S;
                const float* sbk = sb + (k + 1) * LDA_S;
#pragma unroll
                for (int q = 0; q < 4; q++) {
                    float4 v = *(const float4*)(sak + q * 4);
                    fa[cur ^ 1][q * 4 + 0] = v.x; fa[cur ^ 1][q * 4 + 1] = v.y;
                    fa[cur ^ 1][q * 4 + 2] = v.z; fa[cur ^ 1][q * 4 + 3] = v.w;
                }
                ulonglong2 b0 = *(const ulonglong2*)(sbk);
                ulonglong2 b1 = *(const ulonglong2*)(sbk + 4);
                fb[cur ^ 1][0] = b0.x; fb[cur ^ 1][1] = b0.y;
                fb[cur ^ 1][2] = b1.x; fb[cur ^ 1][3] = b1.y;
            }
#pragma unroll
            for (int i = 0; i < 16; i++) {
                u64 ad = dup2(fa[cur][i]);
#pragma unroll
                for (int j = 0; j < 4; j++)
                    ffma2(acc[i][j], ad, fb[cur][j]);
            }
        }

        if (c + 1 < NCk) sts(sm + (s ^ 1) * V4_STAGE);
        __syncthreads();
    }

    const int col0 = bn + tc * 8;
    float bv[8];
#pragma unroll
    for (int j = 0; j < 8; j += 4) {
        float4 b4 = *(const float4*)(bias + col0 + j);
        bv[j] = b4.x; bv[j + 1] = b4.y; bv[j + 2] = b4.z; bv[j + 3] = b4.w;
    }
#pragma unroll
    for (int i = 0; i < 16; i++) {
        float o[8];
#pragma unroll
        for (int j = 0; j < 4; j++) {
            o[2 * j]     = __uint_as_float((unsigned)(acc[i][j] & 0xFFFFFFFFull)) + bv[2 * j];
            o[2 * j + 1] = __uint_as_float((unsigned)(acc[i][j] >> 32)) + bv[2 * j + 1];
            if (RELU) {
                o[2 * j]     = fmaxf(o[2 * j], 0.f);
                o[2 * j + 1] = fmaxf(o[2 * j + 1], 0.f);
            }
        }
        float* crow = C + (size_t)(bm + tr * 16 + i) * N + col0;
        *(float4*)(crow)     = make_float4(o[0], o[1], o[2], o[3]);
        *(float4*)(crow + 4) = make_float4(o[4], o[5], o[6], o[7]);
    }
}

// ---------------------------------------------------------------------------
// v3 (R8): 256 threads, BM=128, thread tile 8 x (BN/16). For L3/L4.
// ---------------------------------------------------------------------------
template<int BN, bool RELU>
__global__ __launch_bounds__(256, 2)
void gemm_v3(const float* __restrict__ A, const float* __restrict__ W,
             const float* __restrict__ bias, float* __restrict__ C,
             int M, int N, int K)
{
    constexpr int TN = BN / 16;
    constexpr int NP = TN / 2;
    constexpr int LDB_S = BN + 4;
    constexpr int ATILE_F = BKC * LDA_S;
    constexpr int BTILE_F = BKC * LDB_S;
    constexpr int STAGE_F = ATILE_F + BTILE_F;
    constexpr int BB4 = BN * BKC / 4;
    constexpr int NB_IT = (BB4 + 255) / 256;

    extern __shared__ float sm[];

    const int tid = threadIdx.x;
    const int tr  = tid >> 4;
    const int tc  = tid & 15;
    const int bm  = blockIdx.y * 128;
    const int bn  = blockIdx.x * BN;
    const int NCk = K / BKC;

    const int lrow = tid >> 2;
    const int lk   = (tid & 3) * 4;

    u64 acc[8][NP];
#pragma unroll
    for (int i = 0; i < 8; i++)
#pragma unroll
        for (int j = 0; j < NP; j++) acc[i][j] = 0ull;

    float4 rA[2], rB[NB_IT];

    auto ldg = [&](int c) {
        const int k0 = c * BKC;
#pragma unroll
        for (int it = 0; it < 2; it++)
            rA[it] = *(const float4*)(A + (size_t)(bm + it * 64 + lrow) * K + k0 + lk);
#pragma unroll
        for (int it = 0; it < NB_IT; it++) {
            int idx = it * 256 + tid;
            if ((BB4 % 256 == 0) || idx < BB4)
                rB[it] = *(const float4*)(W + (size_t)(bn + (idx >> 2)) * K + k0 + lk);
        }
    };
    auto sts = [&](float* st) {
        float* sa = st;
        float* sb = st + ATILE_F;
#pragma unroll
        for (int it = 0; it < 2; it++) {
            float4 v = rA[it];
            int row = it * 64 + lrow;
            sa[(lk + 0) * LDA_S + row] = v.x;
            sa[(lk + 1) * LDA_S + row] = v.y;
            sa[(lk + 2) * LDA_S + row] = v.z;
            sa[(lk + 3) * LDA_S + row] = v.w;
        }
#pragma unroll
        for (int it = 0; it < NB_IT; it++) {
            int idx = it * 256 + tid;
            if ((BB4 % 256 == 0) || idx < BB4) {
                float4 v = rB[it];
                int row = idx >> 2;
                sb[(lk + 0) * LDB_S + row] = v.x;
                sb[(lk + 1) * LDB_S + row] = v.y;
                sb[(lk + 2) * LDB_S + row] = v.z;
                sb[(lk + 3) * LDB_S + row] = v.w;
            }
        }
    };

    ldg(0);
    sts(sm);
    __syncthreads();

    for (int c = 0; c < NCk; c++) {
        const int s = c & 1;
        if (c + 1 < NCk) ldg(c + 1);

        const float* sa = sm + s * STAGE_F + tr * 8;
        const float* sb = sm + s * STAGE_F + ATILE_F + tc * TN;

        float fa[2][8];
        u64   fb[2][NP];
        {
            float4 a0 = *(const float4*)(sa);
            float4 a1 = *(const float4*)(sa + 4);
            fa[0][0] = a0.x; fa[0][1] = a0.y; fa[0][2] = a0.z; fa[0][3] = a0.w;
            fa[0][4] = a1.x; fa[0][5] = a1.y; fa[0][6] = a1.z; fa[0][7] = a1.w;
#pragma unroll
            for (int j = 0; j < NP; j++)
                fb[0][j] = *(const u64*)(sb + 2 * j);
        }
#pragma unroll
        for (int k = 0; k < BKC; k++) {
            const int cur = k & 1;
            if (k + 1 < BKC) {
                const float* sak = sa + (k + 1) * LDA_S;
                const float* sbk = sb + (k + 1) * LDB_S;
                float4 a0 = *(const float4*)(sak);
                float4 a1 = *(const float4*)(sak + 4);
                fa[cur ^ 1][0] = a0.x; fa[cur ^ 1][1] = a0.y;
                fa[cur ^ 1][2] = a0.z; fa[cur ^ 1][3] = a0.w;
                fa[cur ^ 1][4] = a1.x; fa[cur ^ 1][5] = a1.y;
                fa[cur ^ 1][6] = a1.z; fa[cur ^ 1][7] = a1.w;
#pragma unroll
                for (int j = 0; j < NP; j++)
                    fb[cur ^ 1][j] = *(const u64*)(sbk + 2 * j);
            }
#pragma unroll
            for (int i = 0; i < 8; i++) {
                u64 ad = dup2(fa[cur][i]);
#pragma unroll
                for (int j = 0; j < NP; j++)
                    ffma2(acc[i][j], ad, fb[cur][j]);
            }
        }

        if (c + 1 < NCk) sts(sm + (s ^ 1) * STAGE_F);
        __syncthreads();
    }

    const int col0 = bn + tc * TN;
    float bv[TN];
#pragma unroll
    for (int j = 0; j < TN; j++) bv[j] = bias[col0 + j];
#pragma unroll
    for (int i = 0; i < 8; i++) {
        float* crow = C + (size_t)(bm + tr * 8 + i) * N + col0;
#pragma unroll
        for (int j = 0; j < NP; j++) {
            float2 o;
            o.x = __uint_as_float((unsigned)(acc[i][j] & 0xFFFFFFFFull)) + bv[2 * j];
            o.y = __uint_as_float((unsigned)(acc[i][j] >> 32)) + bv[2 * j + 1];
            if (RELU) { o.x = fmaxf(o.x, 0.f); o.y = fmaxf(o.y, 0.f); }
            *(float2*)(crow + 2 * j) = o;
        }
    }
}

// ---------------------------------------------------------------------------
// Wavelet synthesis (recurrence-based, SMEM swizzled) — unchanged.
// ---------------------------------------------------------------------------
#define SYNTH_SMEM (8 * 2048 * 4 + 8 * 32 * 6 * 4 + 8 * 32 * 3 * 8)

__global__ __launch_bounds__(128)
void synth_kernel(const float* __restrict__ P, float* __restrict__ out)
{
    extern __shared__ float sms[];
    float*  acc = sms;
    float*  fp  = sms + 8 * 2048;
    double* dp  = (double*)(fp + 8 * 32 * 6);

    const int tid = threadIdx.x;
    const int b0  = blockIdx.x * 8;

    float4 z4 = make_float4(0.f, 0.f, 0.f, 0.f);
#pragma unroll
    for (int i = tid; i < 8 * 2048 / 4; i += 128)
        ((float4*)acc)[i] = z4;

    for (int p = tid; p < 8 * 32; p += 128) {
        int bl = p >> 5, n = p & 31;
        const float* q = P + (size_t)(b0 + bl) * 160 + n * 5;
        float  a  = q[0];
        double t0 = (1.0 / (1.0 + exp(-(double)q[1]))) * 2048.0;
        double fd = (1.0 / (1.0 + exp(-(double)q[2]))) * 0.5;
        double wd = 6.283185307179586 * fd;
        double sg = (1.0 / (1.0 + exp(-(double)q[3]))) * 200.0 + 2.0;
        double i2 = 1.0 / (2.0 * sg * sg);
        float* f6 = fp + p * 6;
        f6[0] = a;
        f6[1] = (float)i2;
        f6[2] = (float)cos(wd);
        f6[3] = (float)sin(wd);
        f6[4] = (float)exp(-2.0 * i2);
        f6[5] = (float)t0;
        double* d3 = dp + p * 3;
        d3[0] = t0; d3[1] = wd; d3[2] = (double)q[4];
    }
    __syncthreads();

    const int bl  = tid >> 4;
    const int tl  = tid & 15;
    const int col = tid;
    const int   sI = tl * 128;
    const float lo = (float)sI;
    const float hi = lo + 127.f;

    for (int n = 0; n < 32; n++) {
        const float* f6 = fp + (bl * 32 + n) * 6;
        float A = f6[0], i2 = f6[1], cw = f6[2], sw = f6[3], r = f6[4], t0f = f6[5];

        float dn = fmaxf(fmaxf(lo - t0f, t0f - hi), 0.f);
        if (dn * dn * i2 > 18.f) continue;

        float dfar = fmaxf(fabsf(lo - t0f), fabsf(hi - t0f));
        const double* d3 = dp + (bl * 32 + n) * 3;
        double t0d = d3[0], wd = d3[1], phid = d3[2];
        double dtd = (double)sI - t0d;

        if (dfar * dfar * i2 < 55.f) {
            double i2d = (double)i2;
            float g = A * __expf((float)(-dtd * dtd * i2d));
            float u = __expf((float)(-i2d * (2.0 * dtd + 1.0)));
            double ph = fma(wd, dtd, phid);
            double kq = rint(ph * 0.15915494309189535);
            float phr = (float)(ph - kq * 6.283185307179586);
            float c, s;
            __sincosf(phr, &s, &c);
#pragma unroll 4
            for (int i = 0; i < 128; i++) {
                int idx = i * 128 + ((col + i) & 127);
                acc[idx] += g * c;
                float cn  = fmaf(c, cw, -s * sw);
                float snn = fmaf(s, cw,  c * sw);
                c = cn; s = snn;
                g *= u;
                u *= r;
            }
        } else {
            for (int i = 0; i < 128; i++) {
                double dd = dtd + (double)i;
                float dt = (float)dd;
                float e = -dt * dt * i2;
                if (e > -18.f) {
                    double ph = fma(wd, dd, phid);
                    double kq = rint(ph * 0.15915494309189535);
                    float phr = (float)(ph - kq * 6.283185307179586);
                    int idx = i * 128 + ((col + i) & 127);
                    acc[idx] += A * __expf(e) * __cosf(phr);
                }
            }
        }
    }
    __syncthreads();

    for (int e = tid; e < 8 * 2048 / 4; e += 128) {
        int bl2 = e >> 9;
        int t   = (e & 511) * 4;
        int i0  = t & 127;
        int cb  = bl2 * 16 + (t >> 7);
        float4 v;
        v.x = acc[(i0 + 0) * 128 + ((cb + i0 + 0) & 127)];
        v.y = acc[(i0 + 1) * 128 + ((cb + i0 + 1) & 127)];
        v.z = acc[(i0 + 2) * 128 + ((cb + i0 + 2) & 127)];
        v.w = acc[(i0 + 3) * 128 + ((cb + i0 + 3) & 127)];
        size_t ob = ((size_t)(b0 + bl2) * 2) * 2048 + t;
        *(float4*)(out + ob)        = v;
        *(float4*)(out + ob + 2048) = v;
    }
}

// ---------------------------------------------------------------------------
extern "C" void kernel_launch(void* const* d_in, const int* in_sizes, int n_in,
                              void* d_out, int out_size)
{
    const float* x  = (const float*)d_in[0];
    const float* W1 = (const float*)d_in[1];
    const float* b1 = (const float*)d_in[2];
    const float* W2 = (const float*)d_in[3];
    const float* b2 = (const float*)d_in[4];
    const float* W3 = (const float*)d_in[5];
    const float* b3 = (const float*)d_in[6];
    const float* W4 = (const float*)d_in[7];
    const float* b4 = (const float*)d_in[8];
    float* out = (float*)d_out;

    float *h1, *h2, *h3, *pp;
    cudaGetSymbolAddress((void**)&h1, g_h1);
    cudaGetSymbolAddress((void**)&h2, g_h2);
    cudaGetSymbolAddress((void**)&h3, g_h3);
    cudaGetSymbolAddress((void**)&pp, g_p);

    cudaFuncSetAttribute(synth_kernel,
                         cudaFuncAttributeMaxDynamicSharedMemorySize, SYNTH_SMEM);

    const int smem64 = (16 * 132 + 16 * 68) * 2 * 4;   // 25600
    const int smem32 = (16 * 132 + 16 * 36) * 2 * 4;   // 21504

    gemm_v4<true><<<dim3(8, 32), 128, V4_SMEM>>>(
        x, W1, b1, h1, 4096, 1024, 4096);
    gemm_v4<true><<<dim3(4, 32), 128, V4_SMEM>>>(
        h1, W2, b2, h2, 4096, 512, 1024);
    gemm_v3<64, true><<<dim3(4, 32), 256, smem64>>>(
        h2, W3, b3, h3, 4096, 256, 512);
    gemm_v3<32, false><<<dim3(5, 32), 256, smem32>>>(
        h3, W4, b4, pp, 4096, 160, 256);

    synth_kernel<<<4096 / 8, 128, SYNTH_SMEM>>>(pp, out);
}